// round 1
// baseline (speedup 1.0000x reference)
#include <cuda_runtime.h>
#include <cuda_bf16.h>
#include <math.h>

// ---------------------------------------------------------------------------
// MultiheadAttention: b=8, s=1024, d=2048, h=16, hd=128, fp32.
//   q = x@wq^T ; k = x@wk^T ; v = x@wv^T          (8192x2048 @ 2048x2048^T)
//   RoPE over FULL hidden dim on q,k (pairs (2f,2f+1), freq f = col/2)
//   scores = QK^T / sqrt(2048) per (b,h)          (1024x128 @ 128x1024)
//   softmax rows ; ctx = P@V ; out = ctx@wo^T
// ---------------------------------------------------------------------------

#define B_   8
#define S_   1024
#define D_   2048
#define H_   16
#define HD_  128
#define MTOT (B_ * S_)           // 8192

// scratch (no cudaMalloc allowed)
__device__ float g_q  [(size_t)MTOT * D_];
__device__ float g_k  [(size_t)MTOT * D_];
__device__ float g_v  [(size_t)MTOT * D_];
__device__ float g_ctx[(size_t)MTOT * D_];
__device__ float g_p  [(size_t)B_ * H_ * S_ * S_];   // 512 MB scores
__device__ float g_cos[(size_t)S_ * (D_ / 2)];
__device__ float g_sin[(size_t)S_ * (D_ / 2)];

// ---------------------------------------------------------------------------
// RoPE tables: angle = pos * theta^(-2f/d). Computed in double, stored fp32.
// ---------------------------------------------------------------------------
__global__ void rope_tables_k(float* __restrict__ cosT, float* __restrict__ sinT) {
    int idx = blockIdx.x * blockDim.x + threadIdx.x;     // [0, 1024*1024)
    int pos = idx >> 10;
    int f   = idx & 1023;
    double inv = exp(-(double)(2 * f) / (double)D_ * 9.210340371976184);  // ln(10000)
    double a   = (double)pos * inv;
    cosT[idx] = (float)cos(a);
    sinT[idx] = (float)sin(a);
}

// ---------------------------------------------------------------------------
// Tiled SGEMM: C[M,N] = alpha * A @ op(B), 128x128 tile, BK=8, 256 threads,
// 8x8 microtile per thread.
//   TRANSB=true : B is [N,K] row-major (C = A B^T)   -- both operands K-major
//   TRANSB=false: B is [K,N] row-major (C = A B)
//   ROPE=true   : apply full-hidden-dim RoPE rotation in the epilogue
// Batched via blockIdx.z = zb*16 + zh with per-(b)/(h) offsets (0 => unbatched).
// All dims here are multiples of tile sizes: no bounds checks.
// ---------------------------------------------------------------------------
#define TILE 128
#define BK   8

template <bool TRANSB, bool ROPE>
__global__ __launch_bounds__(256)
void gemm_k(const float* __restrict__ A, int lda,
            const float* __restrict__ B, int ldb,
            float* __restrict__ C, int ldc,
            int K, float alpha,
            size_t sAb, size_t sAh, size_t sBb, size_t sBh, size_t sCb, size_t sCh,
            const float* __restrict__ cosT, const float* __restrict__ sinT)
{
    __shared__ float As[BK][TILE];
    __shared__ float Bs[BK][TILE];

    const int z  = blockIdx.z;
    const int zb = z >> 4, zh = z & 15;
    A += (size_t)zb * sAb + (size_t)zh * sAh;
    B += (size_t)zb * sBb + (size_t)zh * sBh;
    C += (size_t)zb * sCb + (size_t)zh * sCh;

    const int t  = threadIdx.x;
    const int tr = t >> 4;          // 0..15 row group
    const int tc = t & 15;          // 0..15 col group
    const int lm = t >> 1;          // 0..127: tile row (A) / tile col (B, NT)
    const int kq = (t & 1) * 4;     // k sub-offset for float4 load

    const float* Aptr = A + (size_t)(blockIdx.y * TILE + lm) * lda + kq;
    const float* Bptr;
    if (TRANSB) {
        Bptr = B + (size_t)(blockIdx.x * TILE + lm) * ldb + kq;
    } else {
        Bptr = B + (size_t)(t >> 5) * ldb + blockIdx.x * TILE + (t & 31) * 4;
    }

    float acc[8][8];
#pragma unroll
    for (int i = 0; i < 8; i++)
#pragma unroll
        for (int j = 0; j < 8; j++) acc[i][j] = 0.f;

    for (int kt = 0; kt < K; kt += BK) {
        float4 av = *(const float4*)(Aptr + kt);
        As[kq + 0][lm] = av.x;
        As[kq + 1][lm] = av.y;
        As[kq + 2][lm] = av.z;
        As[kq + 3][lm] = av.w;
        if (TRANSB) {
            float4 bv = *(const float4*)(Bptr + kt);
            Bs[kq + 0][lm] = bv.x;
            Bs[kq + 1][lm] = bv.y;
            Bs[kq + 2][lm] = bv.z;
            Bs[kq + 3][lm] = bv.w;
        } else {
            float4 bv = *(const float4*)(Bptr + (size_t)kt * ldb);
            *(float4*)&Bs[t >> 5][(t & 31) * 4] = bv;
        }
        __syncthreads();

#pragma unroll
        for (int kk = 0; kk < BK; kk++) {
            float a[8], b[8];
            *(float4*)&a[0] = *(const float4*)&As[kk][tr * 8];
            *(float4*)&a[4] = *(const float4*)&As[kk][tr * 8 + 4];
            *(float4*)&b[0] = *(const float4*)&Bs[kk][tc * 8];
            *(float4*)&b[4] = *(const float4*)&Bs[kk][tc * 8 + 4];
#pragma unroll
            for (int i = 0; i < 8; i++)
#pragma unroll
                for (int j = 0; j < 8; j++)
                    acc[i][j] = fmaf(a[i], b[j], acc[i][j]);
        }
        __syncthreads();
    }

    const int crow = blockIdx.y * TILE + tr * 8;
    const int ccol = blockIdx.x * TILE + tc * 8;
#pragma unroll
    for (int i = 0; i < 8; i++) {
        const int row = crow + i;
        if (ROPE) {
            const int pos = row & (S_ - 1);          // row = b*1024 + s
            const float* cr = cosT + (size_t)pos * (D_ / 2);
            const float* sr = sinT + (size_t)pos * (D_ / 2);
#pragma unroll
            for (int j = 0; j < 8; j += 2) {
                const int f = (ccol + j) >> 1;
                float c = cr[f], s = sr[f];
                float v0 = acc[i][j], v1 = acc[i][j + 1];
                acc[i][j]     = v0 * c - v1 * s;
                acc[i][j + 1] = v0 * s + v1 * c;
            }
        }
        float4 o0 = make_float4(acc[i][0] * alpha, acc[i][1] * alpha,
                                acc[i][2] * alpha, acc[i][3] * alpha);
        float4 o1 = make_float4(acc[i][4] * alpha, acc[i][5] * alpha,
                                acc[i][6] * alpha, acc[i][7] * alpha);
        *(float4*)(C + (size_t)row * ldc + ccol)     = o0;
        *(float4*)(C + (size_t)row * ldc + ccol + 4) = o1;
    }
}

// ---------------------------------------------------------------------------
// Row softmax over 1024 elements: 1 block/row, 256 threads, 1 float4/thread.
// ---------------------------------------------------------------------------
__global__ __launch_bounds__(256)
void softmax_k(float* __restrict__ P) {
    float4* row = (float4*)(P + (size_t)blockIdx.x * S_);
    const int t = threadIdx.x;
    __shared__ float red[256];

    float4 v = row[t];
    float m = fmaxf(fmaxf(v.x, v.y), fmaxf(v.z, v.w));
    red[t] = m;
    __syncthreads();
    for (int s = 128; s > 0; s >>= 1) {
        if (t < s) red[t] = fmaxf(red[t], red[t + s]);
        __syncthreads();
    }
    m = red[0];
    __syncthreads();

    v.x = expf(v.x - m); v.y = expf(v.y - m);
    v.z = expf(v.z - m); v.w = expf(v.w - m);
    red[t] = v.x + v.y + v.z + v.w;
    __syncthreads();
    for (int s = 128; s > 0; s >>= 1) {
        if (t < s) red[t] += red[t + s];
        __syncthreads();
    }
    const float inv = 1.f / red[0];
    v.x *= inv; v.y *= inv; v.z *= inv; v.w *= inv;
    row[t] = v;
}

// ---------------------------------------------------------------------------
extern "C" void kernel_launch(void* const* d_in, const int* in_sizes, int n_in,
                              void* d_out, int out_size) {
    const float* x  = (const float*)d_in[0];
    const float* wq = (const float*)d_in[1];
    const float* wk = (const float*)d_in[2];
    const float* wv = (const float*)d_in[3];
    const float* wo = (const float*)d_in[4];
    float* out = (float*)d_out;

    float *q, *k, *v, *ctx, *p, *ct, *st;
    cudaGetSymbolAddress((void**)&q,   g_q);
    cudaGetSymbolAddress((void**)&k,   g_k);
    cudaGetSymbolAddress((void**)&v,   g_v);
    cudaGetSymbolAddress((void**)&ctx, g_ctx);
    cudaGetSymbolAddress((void**)&p,   g_p);
    cudaGetSymbolAddress((void**)&ct,  g_cos);
    cudaGetSymbolAddress((void**)&st,  g_sin);

    // 1. RoPE tables (1024 x 1024)
    rope_tables_k<<<(S_ * (D_ / 2)) / 256, 256>>>(ct, st);

    // 2. Projections: [8192,2048] = x @ w^T  (NT). RoPE fused for Q,K.
    dim3 gProj(D_ / TILE, MTOT / TILE, 1);   // (16, 64, 1)
    gemm_k<true, true ><<<gProj, 256>>>(x, D_, wq, D_, q, D_, D_, 1.f,
                                        0, 0, 0, 0, 0, 0, ct, st);
    gemm_k<true, true ><<<gProj, 256>>>(x, D_, wk, D_, k, D_, D_, 1.f,
                                        0, 0, 0, 0, 0, 0, ct, st);
    gemm_k<true, false><<<gProj, 256>>>(x, D_, wv, D_, v, D_, D_, 1.f,
                                        0, 0, 0, 0, 0, 0, nullptr, nullptr);

    // 3. scores = Q K^T / sqrt(2048), batched over 128 (b,h). NT, K=128.
    const float alpha = 1.0f / sqrtf((float)D_);
    dim3 gS(S_ / TILE, S_ / TILE, B_ * H_);  // (8, 8, 128)
    gemm_k<true, false><<<gS, 256>>>(q, D_, k, D_, p, S_, HD_, alpha,
                                     (size_t)S_ * D_, (size_t)HD_,
                                     (size_t)S_ * D_, (size_t)HD_,
                                     (size_t)H_ * S_ * S_, (size_t)S_ * S_,
                                     nullptr, nullptr);

    // 4. softmax over last axis (131072 rows of 1024)
    softmax_k<<<B_ * H_ * S_, 256>>>(p);

    // 5. ctx = P @ V, batched. NN (V is [S, hd] with row stride 2048).
    dim3 gC(HD_ / TILE, S_ / TILE, B_ * H_); // (1, 8, 128)
    gemm_k<false, false><<<gC, 256>>>(p, S_, v, D_, ctx, D_, S_, 1.f,
                                      (size_t)H_ * S_ * S_, (size_t)S_ * S_,
                                      (size_t)S_ * D_, (size_t)HD_,
                                      (size_t)S_ * D_, (size_t)HD_,
                                      nullptr, nullptr);

    // 6. out = ctx @ wo^T  (NT)
    gemm_k<true, false><<<gProj, 256>>>(ctx, D_, wo, D_, out, D_, D_, 1.f,
                                        0, 0, 0, 0, 0, 0, nullptr, nullptr);
}